// round 7
// baseline (speedup 1.0000x reference)
#include <cuda_runtime.h>
#include <cstdint>

#define V_     10000
#define VPAD   10240
#define E_     128
#define NTOK   2048
#define NR     8

#define KSPLIT 18
#define KQ     576          // 18*576 = 10368 covers VPAD with guards

// ---------------- scratch (device globals; no allocations) ----------------
__device__ float    g_base[(size_t)NTOK * VPAD];     // q = exp(base)-1 (pad cols = 0)
__device__ uint32_t g_cls4[(size_t)NTOK * (VPAD/8)]; // 4-bit classes, 8 per word; pad = 0
__device__ float    g_colsum[E_];
__device__ float    g_part[40 * E_];
__device__ float    g_spart[2 * NTOK * 18];          // per (half, token): e[8], d[8], B
__device__ float    g_stats[NTOK * 12];              // K1[8], beta
__device__ float    g_psum[KSPLIT][(size_t)NTOK * E_];

__device__ __forceinline__ void fma2(unsigned long long& acc,
                                     unsigned long long a, unsigned long long b) {
    asm("fma.rn.f32x2 %0, %1, %2, %0;" : "+l"(acc) : "l"(a), "l"(b));
}
__device__ __forceinline__ uint32_t s2u(const void* p) {
    return (uint32_t)__cvta_generic_to_shared(p);
}
#define CP_ASYNC16(dst, src) \
    asm volatile("cp.async.cg.shared.global [%0], [%1], 16;\n" :: "r"(dst), "l"(src))
#define CP_COMMIT() asm volatile("cp.async.commit_group;\n" ::: "memory")
#define CP_WAIT0()  asm volatile("cp.async.wait_group 0;\n" ::: "memory")

// ---------------- column sums of W (deterministic 2-stage) ----------------
__global__ void k_colsum1(const float* __restrict__ W) {
    int b = blockIdx.x, col = threadIdx.x;
    float s = 0.f;
    int v0 = b * 250;
    for (int v = v0; v < v0 + 250; v++) s += W[v * E_ + col];
    g_part[b * E_ + col] = s;
}
__global__ void k_colsum2() {
    int col = threadIdx.x;
    float s = 0.f;
    for (int b = 0; b < 40; b++) s += g_part[b * E_ + col];
    g_colsum[col] = s;
}

// ---------------- base GEMM (f32x2, 8x8 tile, double-buffered) + classify ----------------
#define BT 64
#define BV 128
#define KCB 16

// dynamic smem layout (bytes)
#define XBUF_B   (KCB * 132 * 4)           // 8448
#define WBUF_B   (KCB * 132 * 4)           // 8448
#define OFF_XS2  0
#define OFF_WS   (2 * XBUF_B)              // 16896
#define OFF_REL  (OFF_WS + 2 * WBUF_B)     // 33792
#define OFF_EDGE (OFF_REL + 32768)         // 66560
#define OFF_SSM  (OFF_EDGE + 32768)        // 99328
#define SMEM_KB  (OFF_SSM + 256)           // 99584

__global__ __launch_bounds__(128) void k_base(
    const int*   __restrict__ src,
    const float* __restrict__ X,
    const float* __restrict__ W,
    const float* __restrict__ edge,
    const int*   __restrict__ rel)
{
    extern __shared__ char smraw[];
    float (*Xs2)[KCB][132] = (float(*)[KCB][132])(smraw + OFF_XS2);
    float (*Ws)[KCB][132]  = (float(*)[KCB][132])(smraw + OFF_WS);
    int*    rel_s  = (int*)  (smraw + OFF_REL);    // [64 tok][128 v]
    float*  edge_s = (float*)(smraw + OFF_EDGE);   // [64 tok][128 v]
    int*    ssm    = (int*)  (smraw + OFF_SSM);

    int tid  = threadIdx.x;
    int vblk = blockIdx.x * BV;
    int tblk = blockIdx.y * BT;
    if (tid < BT) ssm[tid] = src[tblk + tid];
    __syncthreads();

    // prefetch rel/edge tiles (64 tok x 128 v) via cp.async — hidden under GEMM
    uint32_t rel_su  = s2u(rel_s);
    uint32_t edge_su = s2u(edge_s);
#pragma unroll
    for (int j = 0; j < 16; j++) {
        int chunk = tid + 128 * j;          // 0..2047, 16B chunks
        int tok = chunk >> 5;
        int vloc = (chunk & 31) * 4;
        int v = vblk + vloc;
        if (v < V_) {
            long s = ssm[tok];
            CP_ASYNC16(rel_su  + chunk * 16, rel  + s * (long)V_ + v);
            CP_ASYNC16(edge_su + chunk * 16, edge + s * (long)V_ + v);
        }
    }
    CP_COMMIT();

    unsigned long long acc[8][4];
#pragma unroll
    for (int i = 0; i < 8; i++)
#pragma unroll
        for (int j = 0; j < 4; j++) acc[i][j] = 0ull;

    int tx = tid & 15;     // col group: 8*tx..8*tx+7
    int ty = tid >> 4;     // token group: 8*ty..8*ty+7
    int xtok = tid & 63, xkq = tid >> 6;
    int gvW  = vblk + tid;

    float4 xst[2], wst[4];
    auto stage = [&](int kc) {
#pragma unroll
        for (int j = 0; j < 2; j++) {
            int k4 = 4 * (xkq + 2 * j);
            xst[j] = *(const float4*)&X[(size_t)(tblk + xtok) * E_ + kc + k4];
        }
#pragma unroll
        for (int j = 0; j < 4; j++) {
            wst[j] = (gvW < V_) ? *(const float4*)&W[(size_t)gvW * E_ + kc + 4 * j]
                                : make_float4(0.f, 0.f, 0.f, 0.f);
        }
    };
    auto commit = [&](int buf) {
#pragma unroll
        for (int j = 0; j < 2; j++) {
            int k4 = 4 * (xkq + 2 * j);
            *(float2*)&Xs2[buf][k4 + 0][2 * xtok] = make_float2(xst[j].x, xst[j].x);
            *(float2*)&Xs2[buf][k4 + 1][2 * xtok] = make_float2(xst[j].y, xst[j].y);
            *(float2*)&Xs2[buf][k4 + 2][2 * xtok] = make_float2(xst[j].z, xst[j].z);
            *(float2*)&Xs2[buf][k4 + 3][2 * xtok] = make_float2(xst[j].w, xst[j].w);
        }
#pragma unroll
        for (int j = 0; j < 4; j++) {
            int k4 = 4 * j;
            Ws[buf][k4 + 0][tid] = wst[j].x;
            Ws[buf][k4 + 1][tid] = wst[j].y;
            Ws[buf][k4 + 2][tid] = wst[j].z;
            Ws[buf][k4 + 3][tid] = wst[j].w;
        }
    };

    stage(0);
    commit(0);
    int buf = 0;
#define NCHB (E_ / KCB)   // 8
    for (int ch = 0; ch < NCHB; ch++) {
        __syncthreads();
        if (ch + 1 < NCHB) stage((ch + 1) * KCB);
#pragma unroll
        for (int kk = 0; kk < KCB; kk++) {
            ulonglong2 w01 = *(const ulonglong2*)&Ws[buf][kk][8 * tx];
            ulonglong2 w23 = *(const ulonglong2*)&Ws[buf][kk][8 * tx + 4];
            ulonglong2 a01 = *(const ulonglong2*)&Xs2[buf][kk][16 * ty];
            ulonglong2 a23 = *(const ulonglong2*)&Xs2[buf][kk][16 * ty + 4];
            ulonglong2 a45 = *(const ulonglong2*)&Xs2[buf][kk][16 * ty + 8];
            ulonglong2 a67 = *(const ulonglong2*)&Xs2[buf][kk][16 * ty + 12];
            unsigned long long a[8] = {a01.x, a01.y, a23.x, a23.y,
                                       a45.x, a45.y, a67.x, a67.y};
            unsigned long long w[4] = {w01.x, w01.y, w23.x, w23.y};
#pragma unroll
            for (int i = 0; i < 8; i++)
#pragma unroll
                for (int j = 0; j < 4; j++)
                    fma2(acc[i][j], a[i], w[j]);
        }
        if (ch + 1 < NCHB) commit(buf ^ 1);
        buf ^= 1;
    }

    CP_WAIT0();
    __syncthreads();

    int v0 = vblk + 8 * tx;
#pragma unroll
    for (int i = 0; i < 8; i++) {
        int tl = 8 * ty + i;
        int t  = tblk + tl;
        float2 p0 = *(float2*)&acc[i][0];
        float2 p1 = *(float2*)&acc[i][1];
        float2 p2 = *(float2*)&acc[i][2];
        float2 p3 = *(float2*)&acc[i][3];
        // store q = exp(b) - 1  (pad region: b = 0 -> q = 0)
        float4 q0 = make_float4(__expf(p0.x) - 1.f, __expf(p0.y) - 1.f,
                                __expf(p1.x) - 1.f, __expf(p1.y) - 1.f);
        float4 q1 = make_float4(__expf(p2.x) - 1.f, __expf(p2.y) - 1.f,
                                __expf(p3.x) - 1.f, __expf(p3.y) - 1.f);
        *(float4*)&g_base[(size_t)t * VPAD + v0]     = q0;
        *(float4*)&g_base[(size_t)t * VPAD + v0 + 4] = q1;
        if (v0 < V_) {
            uint32_t pack = 0;
#pragma unroll
            for (int h = 0; h < 2; h++) {
                int vloc = 8 * tx + 4 * h;
                int4   r4 = *(const int4*)  &rel_s [tl * 128 + vloc];
                float4 e4 = *(const float4*)&edge_s[tl * 128 + vloc];
                uint32_t cx = (r4.x >= 1 && r4.x <= 8 && e4.x > 0.f) ? (uint32_t)r4.x : 0u;
                uint32_t cy = (r4.y >= 1 && r4.y <= 8 && e4.y > 0.f) ? (uint32_t)r4.y : 0u;
                uint32_t cz = (r4.z >= 1 && r4.z <= 8 && e4.z > 0.f) ? (uint32_t)r4.z : 0u;
                uint32_t cw = (r4.w >= 1 && r4.w <= 8 && e4.w > 0.f) ? (uint32_t)r4.w : 0u;
                pack |= (cx | (cy << 4) | (cz << 8) | (cw << 12)) << (16 * h);
            }
            g_cls4[(size_t)t * (VPAD/8) + (v0 >> 3)] = pack;
        }
    }
}

// ---------------- stats pass A: per (token, half) partials ----------------
#define CSTRIDE 33

__global__ __launch_bounds__(256) void k_statsA() {
    __shared__ float2 accs[8][9 * CSTRIDE];   // [warp][class*33 + lane]
    __shared__ float  Bsh[8];

    int t   = blockIdx.x;
    int h   = blockIdx.y;
    int tid = threadIdx.x;
    int w   = tid >> 5, lane = tid & 31;

    for (int i = tid; i < 8 * 9 * CSTRIDE; i += 256)
        ((float2*)accs)[i] = make_float2(0.f, 0.f);
    __syncthreads();

    float B = 0.f;
    const float*    qRow = g_base + (size_t)t * VPAD;
    const uint32_t* cRow = g_cls4 + (size_t)t * (VPAD/8);

#pragma unroll
    for (int it = 0; it < 2; it++) {
        int idx = tid + 256 * it;            // chunk within half (16 v each)
        if (idx < 320) {
            int v0 = (h * 320 + idx) * 16;
            float4 q4[4];
#pragma unroll
            for (int j = 0; j < 4; j++) q4[j] = *(const float4*)(qRow + v0 + 4 * j);
            uint2 cp = *(const uint2*)(cRow + (v0 >> 3));
            float qs[16] = {q4[0].x, q4[0].y, q4[0].z, q4[0].w,
                            q4[1].x, q4[1].y, q4[1].z, q4[1].w,
                            q4[2].x, q4[2].y, q4[2].z, q4[2].w,
                            q4[3].x, q4[3].y, q4[3].z, q4[3].w};
            uint32_t cw[2] = {cp.x, cp.y};
#pragma unroll
            for (int j = 0; j < 16; j++) {
                float q = qs[j];
                int   c = (cw[j >> 3] >> (4 * (j & 7))) & 15;
                float b = __logf(fmaxf(q + 1.f, 1e-38f));
                B += b;
                float2* p = &accs[w][c * CSTRIDE + lane];
                float2 o = *p;
                o.x += q;
                o.y = fmaf(q, b, o.y);
                *p = o;
            }
        }
    }
#pragma unroll
    for (int o = 16; o; o >>= 1) B += __shfl_xor_sync(0xFFFFFFFFu, B, o);
    if (lane == 0) Bsh[w] = B;
    __syncthreads();

    // class reduce: warp w handles class w+1
    {
        float2 s = make_float2(0.f, 0.f);
#pragma unroll
        for (int ww = 0; ww < 8; ww++) {
            float2 a = accs[ww][(w + 1) * CSTRIDE + lane];
            s.x += a.x; s.y += a.y;
        }
#pragma unroll
        for (int o = 16; o; o >>= 1) {
            s.x += __shfl_xor_sync(0xFFFFFFFFu, s.x, o);
            s.y += __shfl_xor_sync(0xFFFFFFFFu, s.y, o);
        }
        if (lane == 0) {
            float* sp = g_spart + (size_t)(h * NTOK + t) * 18;
            sp[w]     = s.x;
            sp[8 + w] = s.y;
        }
    }
    if (tid == 0) {
        float Bt = 0.f;
#pragma unroll
        for (int k = 0; k < 8; k++) Bt += Bsh[k];
        g_spart[(size_t)(h * NTOK + t) * 18 + 16] = Bt;
    }
}

// ---------------- stats pass B: combine halves, softmax weights ----------------
__global__ __launch_bounds__(256) void k_statsB() {
    int t = blockIdx.x * 256 + threadIdx.x;
    const float* s0 = g_spart + (size_t)t * 18;
    const float* s1 = g_spart + (size_t)(NTOK + t) * 18;
    float sc[NR], Zv[NR];
    float Bt = s0[16] + s1[16];
#pragma unroll
    for (int r = 0; r < NR; r++) {
        float e = s0[r] + s1[r];
        float d = s0[8 + r] + s1[8 + r];
        float Z = (float)V_ + e;
        Zv[r] = Z;
        sc[r] = (d + Bt) / Z;
    }
    float mx = sc[0];
#pragma unroll
    for (int r = 1; r < NR; r++) mx = fmaxf(mx, sc[r]);
    float es[NR], ss = 0.f;
#pragma unroll
    for (int r = 0; r < NR; r++) { es[r] = __expf(sc[r] - mx); ss += es[r]; }
    float inv = 1.f / ss;
    float beta = 0.f;
    float* st = g_stats + t * 12;
#pragma unroll
    for (int r = 0; r < NR; r++) {
        float K1 = es[r] * inv / Zv[r];
        st[r] = K1;
        beta += K1;
    }
    st[8] = beta;
}

// ---------------- final GEMM: gamma = K1[c]*q, 8x8 tile, double-buffered ----------------
#define BMF  64
#define KCF  16
#define NCHF (KQ / KCF)      // 36

__global__ __launch_bounds__(128) void k_final(const float* __restrict__ W) {
    __shared__ float Ws[2][KCF][E_];
    __shared__ float As2[2][KCF][132];
    __shared__ float K1s[BMF][NR];

    int tid = threadIdx.x;
    int t0  = blockIdx.x * BMF;
    int ks  = blockIdx.y;
    int k0  = ks * KQ;

#pragma unroll
    for (int j = 0; j < 4; j++) {
        int idx = tid + 128 * j;
        K1s[idx >> 3][idx & 7] = g_stats[(t0 + (idx >> 3)) * 12 + (idx & 7)];
    }
    __syncthreads();

    unsigned long long acc[8][4];
#pragma unroll
    for (int i = 0; i < 8; i++)
#pragma unroll
        for (int j = 0; j < 4; j++) acc[i][j] = 0ull;

    int tx = tid & 15, ty = tid >> 4;
    int tokA = tid >> 1, kA = (tid & 1) * 8;

    float4   wst[4];
    float4   bst[2];
    uint32_t cst;

    auto stage = [&](int kc) {
#pragma unroll
        for (int j = 0; j < 4; j++) {
            int p  = tid + 128 * j;
            int v  = p >> 5;
            int e4 = (p & 31) * 4;
            int gv = kc + v;
            wst[j] = (gv < V_) ? *(const float4*)&W[(size_t)gv * E_ + e4]
                               : make_float4(0.f, 0.f, 0.f, 0.f);
        }
        int gb = kc + kA;
        if (gb < V_) {
            size_t off = (size_t)(t0 + tokA) * VPAD + gb;
            bst[0] = *(const float4*)(g_base + off);
            bst[1] = *(const float4*)(g_base + off + 4);
            cst    = g_cls4[(size_t)(t0 + tokA) * (VPAD/8) + (gb >> 3)];
        } else {
            bst[0] = bst[1] = make_float4(0.f, 0.f, 0.f, 0.f);
            cst = 0;
        }
    };
    auto commit = [&](int buf) {
#pragma unroll
        for (int j = 0; j < 4; j++) {
            int p  = tid + 128 * j;
            int v  = p >> 5;
            int e4 = (p & 31) * 4;
            *(float4*)&Ws[buf][v][e4] = wst[j];
        }
        float qq[8] = {bst[0].x, bst[0].y, bst[0].z, bst[0].w,
                       bst[1].x, bst[1].y, bst[1].z, bst[1].w};
#pragma unroll
        for (int j = 0; j < 8; j++) {
            int c = (cst >> (4 * j)) & 15;
            float g = c ? K1s[tokA][c - 1] * qq[j] : 0.f;
            *(float2*)&As2[buf][kA + j][2 * tokA] = make_float2(g, g);
        }
    };

    stage(k0);
    commit(0);
    int buf = 0;

    for (int i = 0; i < NCHF; i++) {
        __syncthreads();
        if (i + 1 < NCHF) stage(k0 + (i + 1) * KCF);
#pragma unroll
        for (int kk = 0; kk < KCF; kk++) {
            ulonglong2 w01 = *(const ulonglong2*)&Ws[buf][kk][8 * tx];
            ulonglong2 w23 = *(const ulonglong2*)&Ws[buf][kk][8 * tx + 4];
            ulonglong2 a01 = *(const ulonglong2*)&As2[buf][kk][16 * ty];
            ulonglong2 a23 = *(const ulonglong2*)&As2[buf][kk][16 * ty + 4];
            ulonglong2 a45 = *(const ulonglong2*)&As2[buf][kk][16 * ty + 8];
            ulonglong2 a67 = *(const ulonglong2*)&As2[buf][kk][16 * ty + 12];
            unsigned long long a[8] = {a01.x, a01.y, a23.x, a23.y,
                                       a45.x, a45.y, a67.x, a67.y};
            unsigned long long w[4] = {w01.x, w01.y, w23.x, w23.y};
#pragma unroll
            for (int ii = 0; ii < 8; ii++)
#pragma unroll
                for (int jj = 0; jj < 4; jj++)
                    fma2(acc[ii][jj], a[ii], w[jj]);
        }
        if (i + 1 < NCHF) commit(buf ^ 1);
        buf ^= 1;
    }

    float* ps = g_psum[ks];
#pragma unroll
    for (int i = 0; i < 8; i++) {
        int t = t0 + 8 * ty + i;
        float2 p0 = *(float2*)&acc[i][0];
        float2 p1 = *(float2*)&acc[i][1];
        float2 p2 = *(float2*)&acc[i][2];
        float2 p3 = *(float2*)&acc[i][3];
        *(float4*)&ps[(size_t)t * E_ + 8 * tx]     = make_float4(p0.x, p0.y, p1.x, p1.y);
        *(float4*)&ps[(size_t)t * E_ + 8 * tx + 4] = make_float4(p2.x, p2.y, p3.x, p3.y);
    }
}

// ---------------- combine K-split partials + background term ----------------
__global__ void k_combine(float* __restrict__ out) {
    int i  = blockIdx.x * 256 + threadIdx.x;
    int t  = i >> 5;
    int c4 = (i & 31) * 4;
    size_t off = (size_t)t * E_ + c4;
    float  beta = g_stats[t * 12 + 8];
    float4 cs = *(const float4*)&g_colsum[c4];
    float4 o = make_float4(beta * cs.x, beta * cs.y, beta * cs.z, beta * cs.w);
#pragma unroll
    for (int r = 0; r < KSPLIT; r++) {
        float4 a = *(const float4*)&g_psum[r][off];
        o.x += a.x; o.y += a.y; o.z += a.z; o.w += a.w;
    }
    *(float4*)&out[off] = o;
}

// ---------------- launch ----------------
extern "C" void kernel_launch(void* const* d_in, const int* in_sizes, int n_in,
                              void* d_out, int out_size) {
    const int*   src  = (const int*)  d_in[0];
    const float* X    = (const float*)d_in[1];
    const float* W    = (const float*)d_in[2];
    const float* edge = (const float*)d_in[3];
    const int*   rel  = (const int*)  d_in[4];
    float* out = (float*)d_out;

    cudaFuncSetAttribute(k_base, cudaFuncAttributeMaxDynamicSharedMemorySize, SMEM_KB);

    k_colsum1<<<40, 128>>>(W);
    k_colsum2<<<1, 128>>>();

    dim3 gb((V_ + BV - 1) / BV, NTOK / BT);   // 79 x 32
    k_base<<<gb, 128, SMEM_KB>>>(src, X, W, edge, rel);

    k_statsA<<<dim3(NTOK, 2), 256>>>();
    k_statsB<<<NTOK / 256, 256>>>();

    k_final<<<dim3(NTOK / BMF, KSPLIT), 128>>>(W);  // 32 x 18 = 576 CTAs

    k_combine<<<256, 256>>>(out);
    (void)in_sizes; (void)n_in; (void)out_size;
}